// round 12
// baseline (speedup 1.0000x reference)
#include <cuda_runtime.h>
#include <cstdint>

#define B_ 2
#define S_ 4096
#define E_ 1024
#define H_ 16
#define D_ 64
#define W_ 256

// Scratch (static device arrays — no allocs)
__device__ float g_q[(size_t)B_ * H_ * S_ * D_];
__device__ float g_k[(size_t)B_ * H_ * S_ * D_];
__device__ float g_v[(size_t)B_ * H_ * S_ * D_];
// tf32-pre-rounded copies of X and weights
__device__ uint32_t g_xt[(size_t)B_ * S_ * E_];      // [8192][1024]
__device__ uint32_t g_wqt[(size_t)E_ * E_];
__device__ uint32_t g_wkt[(size_t)E_ * E_];
__device__ uint32_t g_wvt[(size_t)E_ * E_];

// ---------------------------------------------------------------------------
// helpers
// ---------------------------------------------------------------------------
__device__ __forceinline__ uint32_t f2tf(float x) {
    uint32_t r;
    asm("cvt.rna.tf32.f32 %0, %1;" : "=r"(r) : "f"(x));
    return r;
}

__device__ __forceinline__ void mma8(float c[4],
                                     uint32_t a0, uint32_t a1, uint32_t a2, uint32_t a3,
                                     uint32_t b0, uint32_t b1) {
    asm volatile(
        "mma.sync.aligned.m16n8k8.row.col.f32.tf32.tf32.f32 "
        "{%0,%1,%2,%3}, {%4,%5,%6,%7}, {%8,%9}, {%0,%1,%2,%3};"
        : "+f"(c[0]), "+f"(c[1]), "+f"(c[2]), "+f"(c[3])
        : "r"(a0), "r"(a1), "r"(a2), "r"(a3), "r"(b0), "r"(b1));
}

__device__ __forceinline__ void cpa16(uint32_t smem_addr, const void* gmem) {
    asm volatile("cp.async.cg.shared.global [%0], [%1], 16;"
                 :: "r"(smem_addr), "l"(gmem));
}
__device__ __forceinline__ void cpa_commit() {
    asm volatile("cp.async.commit_group;");
}
template <int N>
__device__ __forceinline__ void cpa_wait() {
    asm volatile("cp.async.wait_group %0;" :: "n"(N));
}

// ---------------------------------------------------------------------------
// Kernel 0: elementwise fp32 -> tf32(rna) pre-conversion (vectorized x4).
// ---------------------------------------------------------------------------
__global__ __launch_bounds__(256)
void conv_tf32(const float* __restrict__ src, uint32_t* __restrict__ dst, int n4)
{
    int i = blockIdx.x * 256 + threadIdx.x;
    if (i < n4) {
        float4 v = ((const float4*)src)[i];
        uint4 o;
        o.x = f2tf(v.x); o.y = f2tf(v.y); o.z = f2tf(v.z); o.w = f2tf(v.w);
        ((uint4*)dst)[i] = o;
    }
}

// ---------------------------------------------------------------------------
// Kernel 1: fused QKV projection, tf32 mma, cp.async double-buffered.
// C[M=8192,N=1024] = Xt @ Wt^T (+bias, q*1/8), scattered to [B,H,S,D].
// Block 256 threads (8 warps), tile 128x128, BK=16.
// Warp w: (w&1)*64 rows x (w>>1)*32 cols; 4x4 grid of m16n8k8.
// Smem natural [row][k] tf32, stride 20 -> conflict-free fragment LDS.
// ---------------------------------------------------------------------------
__global__ __launch_bounds__(256)
void qkv_gemm_tf32(const float* __restrict__ bq,
                   const float* __restrict__ bk,
                   const float* __restrict__ bv)
{
    const uint32_t* Wa; const float* bias; float* outp; float scale;
    if (blockIdx.z == 0)      { Wa = g_wqt; bias = bq; outp = g_q; scale = 0.125f; }
    else if (blockIdx.z == 1) { Wa = g_wkt; bias = bk; outp = g_k; scale = 1.0f;   }
    else                      { Wa = g_wvt; bias = bv; outp = g_v; scale = 1.0f;   }

    __shared__ uint32_t sA[2][128][20];   // [buf][m][k] tf32 (+4 pad)
    __shared__ uint32_t sB[2][128][20];   // [buf][n][k] tf32

    const int m0   = blockIdx.x * 128;
    const int n0   = blockIdx.y * 128;
    const int tid  = threadIdx.x;
    const int lane = tid & 31;
    const int wid  = tid >> 5;
    const int wm   = wid & 1;
    const int wn   = wid >> 1;
    const int lg   = lane >> 2;
    const int lt   = lane & 3;

    // staging mapping: thread t covers row sr, k-chunks sc and sc+4
    const int sr = tid >> 1;            // 0..127
    const int sc = (tid & 1) << 3;      // 0 or 8

    const uint32_t* agm = g_xt + (size_t)(m0 + sr) * E_ + sc;
    const uint32_t* bgm = Wa   + (size_t)(n0 + sr) * E_ + sc;

    const uint32_t sA_base = (uint32_t)__cvta_generic_to_shared(&sA[0][0][0]);
    const uint32_t sB_base = (uint32_t)__cvta_generic_to_shared(&sB[0][0][0]);
    const uint32_t doff    = (uint32_t)(sr * 20 + sc) * 4;   // bytes within buffer
    const uint32_t BUFSZ   = 128 * 20 * 4;                   // 10240 B

    float c[4][4][4];
    #pragma unroll
    for (int i = 0; i < 4; i++)
        #pragma unroll
        for (int j = 0; j < 4; j++)
            #pragma unroll
            for (int r = 0; r < 4; r++) c[i][j][r] = 0.f;

    // prologue: stage tile 0 into buf 0
    cpa16(sA_base + doff,      agm);
    cpa16(sA_base + doff + 16, agm + 4);
    cpa16(sB_base + doff,      bgm);
    cpa16(sB_base + doff + 16, bgm + 4);
    cpa_commit();

    for (int kt = 0; kt < 64; kt++) {
        const int buf = kt & 1;
        if (kt < 63) {
            const uint32_t bo = (uint32_t)(1 - buf) * BUFSZ;
            const int k0 = (kt + 1) * 16;
            cpa16(sA_base + bo + doff,      agm + k0);
            cpa16(sA_base + bo + doff + 16, agm + k0 + 4);
            cpa16(sB_base + bo + doff,      bgm + k0);
            cpa16(sB_base + bo + doff + 16, bgm + k0 + 4);
            cpa_commit();
            cpa_wait<1>();
        } else {
            cpa_wait<0>();
        }
        __syncthreads();

        #pragma unroll
        for (int ks = 0; ks < 2; ks++) {
            const int k8 = ks * 8;
            uint32_t a[4][4], bf[4][2];
            #pragma unroll
            for (int mt = 0; mt < 4; mt++) {
                const int mrow = wm * 64 + mt * 16 + lg;
                a[mt][0] = sA[buf][mrow][k8 + lt];
                a[mt][1] = sA[buf][mrow + 8][k8 + lt];
                a[mt][2] = sA[buf][mrow][k8 + lt + 4];
                a[mt][3] = sA[buf][mrow + 8][k8 + lt + 4];
            }
            #pragma unroll
            for (int nt = 0; nt < 4; nt++) {
                const int ncol = wn * 32 + nt * 8 + lg;
                bf[nt][0] = sB[buf][ncol][k8 + lt];
                bf[nt][1] = sB[buf][ncol][k8 + lt + 4];
            }
            #pragma unroll
            for (int mt = 0; mt < 4; mt++)
                #pragma unroll
                for (int nt = 0; nt < 4; nt++)
                    mma8(c[mt][nt], a[mt][0], a[mt][1], a[mt][2], a[mt][3],
                         bf[nt][0], bf[nt][1]);
        }
        __syncthreads();
    }

    // Epilogue: bias + scale, scatter to [B,H,S,D]
    #pragma unroll
    for (int nt = 0; nt < 4; nt++) {
        const int n = n0 + wn * 32 + nt * 8 + (lt << 1);
        const int h = n >> 6;
        const int d = n & 63;
        const float b0v = bias[n], b1v = bias[n + 1];
        #pragma unroll
        for (int mt = 0; mt < 4; mt++) {
            #pragma unroll
            for (int half = 0; half < 2; half++) {
                const int m  = m0 + wm * 64 + mt * 16 + lg + half * 8;
                const int bb = m >> 12;
                const int s  = m & (S_ - 1);
                float2 o;
                o.x = (c[mt][nt][half * 2 + 0] + b0v) * scale;
                o.y = (c[mt][nt][half * 2 + 1] + b1v) * scale;
                *(float2*)(outp + (((size_t)bb * H_ + h) * S_ + s) * D_ + d) = o;
            }
        }
    }
}

// ---------------------------------------------------------------------------
// Kernel 2: banded attention, tensor-core tf32 mma for QK^T and PV.
// (unchanged from R9 — 189us, L1 66%, tensor 33%)
// ---------------------------------------------------------------------------
__global__ __launch_bounds__(128)
void banded_attn_tc(const int* __restrict__ amask, float* __restrict__ out)
{
    __shared__ uint32_t Ks[64][68];   // tf32, natural [key][d]
    __shared__ uint32_t Vs[64][72];   // tf32, natural [key][d]
    __shared__ float    am_s[64];     // additive mask per key of current tile

    const int q0 = blockIdx.x * 64;
    const int h  = blockIdx.y;
    const int b  = blockIdx.z;

    const int tid  = threadIdx.x;
    const int lane = tid & 31;
    const int wid  = tid >> 5;        // 0..3
    const int lg   = lane >> 2;       // 0..7
    const int lt   = lane & 3;        // 0..3

    const size_t head_off = (((size_t)b * H_ + h) * S_) * D_;
    const float* kb_ = g_k + head_off;
    const float* vb_ = g_v + head_off;

    const int qi0 = q0 + wid * 16 + lg;
    const int qi1 = qi0 + 8;
    const float* qr0 = g_q + head_off + (size_t)qi0 * D_;
    const float* qr1 = qr0 + 8 * D_;

    uint32_t qf[8][4];
    #pragma unroll
    for (int ks = 0; ks < 8; ks++) {
        qf[ks][0] = f2tf(qr0[ks * 8 + lt]);
        qf[ks][1] = f2tf(qr1[ks * 8 + lt]);
        qf[ks][2] = f2tf(qr0[ks * 8 + lt + 4]);
        qf[ks][3] = f2tf(qr1[ks * 8 + lt + 4]);
    }

    const int lo0 = max(0, qi0 - W_), hi0 = min(S_ - 1, qi0 + W_);
    const int lo1 = max(0, qi1 - W_), hi1 = min(S_ - 1, qi1 + W_);

    float m0r = -1e30f, m1r = -1e30f, l0 = 0.f, l1 = 0.f;
    float oacc[8][4];
    #pragma unroll
    for (int vn = 0; vn < 8; vn++)
        #pragma unroll
        for (int r = 0; r < 4; r++) oacc[vn][r] = 0.f;

    for (int t = 0; t < 9; t++) {
        const int kt0 = q0 - W_ + t * 64;
        if (kt0 + 63 < 0 || kt0 >= S_) continue;

        __syncthreads();

        #pragma unroll
        for (int it = 0; it < 8; it++) {
            int idx = tid + it * 128;
            int r   = idx >> 4;
            int d4  = (idx & 15) << 2;
            int jg  = kt0 + r;
            float4 kv = make_float4(0.f, 0.f, 0.f, 0.f);
            float4 vv = make_float4(0.f, 0.f, 0.f, 0.f);
            if (jg >= 0 && jg < S_) {
                kv = *(const float4*)(kb_ + (size_t)jg * D_ + d4);
                vv = *(const float4*)(vb_ + (size_t)jg * D_ + d4);
            }
            uint4 kt4, vt4;
            kt4.x = f2tf(kv.x); kt4.y = f2tf(kv.y); kt4.z = f2tf(kv.z); kt4.w = f2tf(kv.w);
            vt4.x = f2tf(vv.x); vt4.y = f2tf(vv.y); vt4.z = f2tf(vv.z); vt4.w = f2tf(vv.w);
            *(uint4*)&Ks[r][d4] = kt4;
            *(uint4*)&Vs[r][d4] = vt4;
        }
        if (tid < 64) {
            int jg = kt0 + tid;
            am_s[tid] = (jg >= 0 && jg < S_ && amask[b * S_ + jg] != 0) ? -10000.f : 0.f;
        }
        __syncthreads();

        float s[8][4];
        #pragma unroll
        for (int nt = 0; nt < 8; nt++)
            #pragma unroll
            for (int r = 0; r < 4; r++) s[nt][r] = 0.f;

        #pragma unroll
        for (int ks = 0; ks < 8; ks++) {
            const int k8 = ks * 8;
            #pragma unroll
            for (int nt = 0; nt < 8; nt++) {
                uint32_t b0 = Ks[nt * 8 + lg][k8 + lt];
                uint32_t b1 = Ks[nt * 8 + lg][k8 + lt + 4];
                mma8(s[nt], qf[ks][0], qf[ks][1], qf[ks][2], qf[ks][3], b0, b1);
            }
        }

        float tmax0 = -1e30f, tmax1 = -1e30f;
        #pragma unroll
        for (int nt = 0; nt < 8; nt++) {
            const int c0  = (nt << 3) + (lt << 1);
            const int jg0 = kt0 + c0, jg1 = jg0 + 1;
            const float am0 = am_s[c0], am1 = am_s[c0 + 1];
            s[nt][0] = (jg0 >= lo0 && jg0 <= hi0) ? s[nt][0] + am0 : -1e30f;
            s[nt][1] = (jg1 >= lo0 && jg1 <= hi0) ? s[nt][1] + am1 : -1e30f;
            s[nt][2] = (jg0 >= lo1 && jg0 <= hi1) ? s[nt][2] + am0 : -1e30f;
            s[nt][3] = (jg1 >= lo1 && jg1 <= hi1) ? s[nt][3] + am1 : -1e30f;
            tmax0 = fmaxf(tmax0, fmaxf(s[nt][0], s[nt][1]));
            tmax1 = fmaxf(tmax1, fmaxf(s[nt][2], s[nt][3]));
        }
        tmax0 = fmaxf(tmax0, __shfl_xor_sync(0xffffffffu, tmax0, 1, 32));
        tmax0 = fmaxf(tmax0, __shfl_xor_sync(0xffffffffu, tmax0, 2, 32));
        tmax1 = fmaxf(tmax1, __shfl_xor_sync(0xffffffffu, tmax1, 1, 32));
        tmax1 = fmaxf(tmax1, __shfl_xor_sync(0xffffffffu, tmax1, 2, 32));

        const float mn0 = fmaxf(m0r, tmax0), mn1 = fmaxf(m1r, tmax1);
        const float corr0 = __expf(m0r - mn0), corr1 = __expf(m1r - mn1);

        float rs0 = 0.f, rs1 = 0.f;
        #pragma unroll
        for (int nt = 0; nt < 8; nt++) {
            float e0 = (s[nt][0] > -1e29f) ? __expf(s[nt][0] - mn0) : 0.f;
            float e1 = (s[nt][1] > -1e29f) ? __expf(s[nt][1] - mn0) : 0.f;
            float e2 = (s[nt][2] > -1e29f) ? __expf(s[nt][2] - mn1) : 0.f;
            float e3 = (s[nt][3] > -1e29f) ? __expf(s[nt][3] - mn1) : 0.f;
            s[nt][0] = e0; s[nt][1] = e1; s[nt][2] = e2; s[nt][3] = e3;
            rs0 += e0 + e1; rs1 += e2 + e3;
        }
        rs0 += __shfl_xor_sync(0xffffffffu, rs0, 1, 32);
        rs0 += __shfl_xor_sync(0xffffffffu, rs0, 2, 32);
        rs1 += __shfl_xor_sync(0xffffffffu, rs1, 1, 32);
        rs1 += __shfl_xor_sync(0xffffffffu, rs1, 2, 32);

        l0 = l0 * corr0 + rs0; m0r = mn0;
        l1 = l1 * corr1 + rs1; m1r = mn1;
        #pragma unroll
        for (int vn = 0; vn < 8; vn++) {
            oacc[vn][0] *= corr0; oacc[vn][1] *= corr0;
            oacc[vn][2] *= corr1; oacc[vn][3] *= corr1;
        }

        const int s0l = (lg << 2) + (lt >> 1);
        const int s1l = s0l + 2;
        const bool odd = (lt & 1);
        #pragma unroll
        for (int kk = 0; kk < 8; kk++) {
            float t00 = __shfl_sync(0xffffffffu, s[kk][0], s0l, 32);
            float t01 = __shfl_sync(0xffffffffu, s[kk][1], s0l, 32);
            float t10 = __shfl_sync(0xffffffffu, s[kk][2], s0l, 32);
            float t11 = __shfl_sync(0xffffffffu, s[kk][3], s0l, 32);
            float t20 = __shfl_sync(0xffffffffu, s[kk][0], s1l, 32);
            float t21 = __shfl_sync(0xffffffffu, s[kk][1], s1l, 32);
            float t30 = __shfl_sync(0xffffffffu, s[kk][2], s1l, 32);
            float t31 = __shfl_sync(0xffffffffu, s[kk][3], s1l, 32);
            uint32_t a0 = f2tf(odd ? t01 : t00);
            uint32_t a1 = f2tf(odd ? t11 : t10);
            uint32_t a2 = f2tf(odd ? t21 : t20);
            uint32_t a3 = f2tf(odd ? t31 : t30);
            const int k8 = kk * 8;
            #pragma unroll
            for (int vn = 0; vn < 8; vn++) {
                uint32_t b0 = Vs[k8 + lt][vn * 8 + lg];
                uint32_t b1 = Vs[k8 + lt + 4][vn * 8 + lg];
                mma8(oacc[vn], a0, a1, a2, a3, b0, b1);
            }
        }
    }

    const float inv0 = 1.f / l0, inv1 = 1.f / l1;
    float* o0 = out + ((size_t)b * S_ + qi0) * E_ + h * D_;
    float* o1 = out + ((size_t)b * S_ + qi1) * E_ + h * D_;
    #pragma unroll
    for (int vn = 0; vn < 8; vn++) {
        const int col = vn * 8 + (lt << 1);
        float2 r0, r1;
        r0.x = oacc[vn][0] * inv0; r0.y = oacc[vn][1] * inv0;
        r1.x = oacc[vn][2] * inv1; r1.y = oacc[vn][3] * inv1;
        *(float2*)(o0 + col) = r0;
        *(float2*)(o1 + col) = r1;
    }
}

// ---------------------------------------------------------------------------
extern "C" void kernel_launch(void* const* d_in, const int* in_sizes, int n_in,
                              void* d_out, int out_size)
{
    const float* hs    = (const float*)d_in[0];   // [B,S,E]
    const int*   amask = (const int*)  d_in[1];   // [B,S]
    const float* qw    = (const float*)d_in[2];
    const float* qb    = (const float*)d_in[3];
    const float* kw    = (const float*)d_in[4];
    const float* kb    = (const float*)d_in[5];
    const float* vw    = (const float*)d_in[6];
    const float* vb    = (const float*)d_in[7];
    float* out = (float*)d_out;

    uint32_t *xt, *wqt, *wkt, *wvt;
    cudaGetSymbolAddress((void**)&xt,  g_xt);
    cudaGetSymbolAddress((void**)&wqt, g_wqt);
    cudaGetSymbolAddress((void**)&wkt, g_wkt);
    cudaGetSymbolAddress((void**)&wvt, g_wvt);

    const int nx4 = (B_ * S_ * E_) / 4;      // 2,097,152
    const int nw4 = (E_ * E_) / 4;           // 262,144
    conv_tf32<<<(nx4 + 255) / 256, 256>>>(hs, xt, nx4);
    conv_tf32<<<(nw4 + 255) / 256, 256>>>(qw, wqt, nw4);
    conv_tf32<<<(nw4 + 255) / 256, 256>>>(kw, wkt, nw4);
    conv_tf32<<<(nw4 + 255) / 256, 256>>>(vw, wvt, nw4);

    dim3 g1((B_ * S_) / 128, E_ / 128, 3);   // 64 x 8 x 3
    qkv_gemm_tf32<<<g1, 256>>>(qb, kb, vb);

    dim3 g2(S_ / 64, H_, B_);                // 64 x 16 x 2
    banded_attn_tc<<<g2, 128>>>(amask, out);
}

// round 14
// speedup vs baseline: 1.3814x; 1.3814x over previous
#include <cuda_runtime.h>
#include <cstdint>

#define B_ 2
#define S_ 4096
#define E_ 1024
#define H_ 16
#define D_ 64
#define W_ 256

// Scratch: q/k/v in [B,H,S,D] layout (static device arrays — no allocs)
__device__ float g_q[(size_t)B_ * H_ * S_ * D_];
__device__ float g_k[(size_t)B_ * H_ * S_ * D_];
__device__ float g_v[(size_t)B_ * H_ * S_ * D_];

// ---------------------------------------------------------------------------
// tf32 helpers
// ---------------------------------------------------------------------------
__device__ __forceinline__ uint32_t f2tf(float x) {
    uint32_t r;
    asm("cvt.rna.tf32.f32 %0, %1;" : "=r"(r) : "f"(x));
    return r;
}

__device__ __forceinline__ void mma8(float c[4],
                                     uint32_t a0, uint32_t a1, uint32_t a2, uint32_t a3,
                                     uint32_t b0, uint32_t b1) {
    asm volatile(
        "mma.sync.aligned.m16n8k8.row.col.f32.tf32.tf32.f32 "
        "{%0,%1,%2,%3}, {%4,%5,%6,%7}, {%8,%9}, {%0,%1,%2,%3};"
        : "+f"(c[0]), "+f"(c[1]), "+f"(c[2]), "+f"(c[3])
        : "r"(a0), "r"(a1), "r"(a2), "r"(a3), "r"(b0), "r"(b1));
}

// ---------------------------------------------------------------------------
// Kernel 1: fused QKV projection with tf32 tensor-core MMA.
// C[M=8192,N=1024] = X @ W^T + b (q additionally * 1/8), scattered to [B,H,S,D].
// Block 256 threads (8 warps), tile 128x128, BK=16, single-buffered with
// register prefetch (R9 structure). Changes vs R9:
//   * __launch_bounds__(256, 2) -> 2 blocks/SM so a co-resident block's MMAs
//     hide this block's store/sync phases.
//   * smem natural [row][k] tf32, stride 20: STS.128 stores (<=2-way conflict,
//     vs R9's 4-way STS.32) and provably conflict-free fragment LDS
//     (bank = (20*lg + lt) mod 32 covers all 32 banks).
// ---------------------------------------------------------------------------
__global__ __launch_bounds__(256, 2)
void qkv_gemm_tf32(const float* __restrict__ X,
                   const float* __restrict__ Wq, const float* __restrict__ bq,
                   const float* __restrict__ Wk, const float* __restrict__ bk,
                   const float* __restrict__ Wv, const float* __restrict__ bv)
{
    const float* Wt; const float* bias; float* outp; float scale;
    if (blockIdx.z == 0)      { Wt = Wq; bias = bq; outp = g_q; scale = 0.125f; }
    else if (blockIdx.z == 1) { Wt = Wk; bias = bk; outp = g_k; scale = 1.0f;   }
    else                      { Wt = Wv; bias = bv; outp = g_v; scale = 1.0f;   }

    __shared__ uint32_t sA[128][20];   // [m][k] tf32 (+4 pad)
    __shared__ uint32_t sB[128][20];   // [n][k] tf32

    const int m0   = blockIdx.x * 128;
    const int n0   = blockIdx.y * 128;
    const int tid  = threadIdx.x;
    const int lane = tid & 31;
    const int wid  = tid >> 5;
    const int wm   = wid & 1;          // 64-row band
    const int wn   = wid >> 1;         // 32-col band
    const int lg   = lane >> 2;        // 0..7
    const int lt   = lane & 3;         // 0..3

    // staging mapping: thread covers row sr, k-words sc..sc+7 (two float4)
    const int sr = tid >> 1;           // 0..127
    const int sc = (tid & 1) << 3;     // 0 or 8

    const float* xp = X  + (size_t)(m0 + sr) * E_ + sc;
    const float* wp = Wt + (size_t)(n0 + sr) * E_ + sc;

    float c[4][4][4];
    #pragma unroll
    for (int i = 0; i < 4; i++)
        #pragma unroll
        for (int j = 0; j < 4; j++)
            #pragma unroll
            for (int r = 0; r < 4; r++) c[i][j][r] = 0.f;

    // Prefetch first K-tile into registers
    float4 fx0 = *(const float4*)(xp);
    float4 fx1 = *(const float4*)(xp + 4);
    float4 fw0 = *(const float4*)(wp);
    float4 fw1 = *(const float4*)(wp + 4);

    for (int kt = 0; kt < 64; kt++) {
        __syncthreads();   // previous tile's fragment reads complete
        {
            uint4 t;
            t.x = f2tf(fx0.x); t.y = f2tf(fx0.y); t.z = f2tf(fx0.z); t.w = f2tf(fx0.w);
            *(uint4*)&sA[sr][sc] = t;
            t.x = f2tf(fx1.x); t.y = f2tf(fx1.y); t.z = f2tf(fx1.z); t.w = f2tf(fx1.w);
            *(uint4*)&sA[sr][sc + 4] = t;
            t.x = f2tf(fw0.x); t.y = f2tf(fw0.y); t.z = f2tf(fw0.z); t.w = f2tf(fw0.w);
            *(uint4*)&sB[sr][sc] = t;
            t.x = f2tf(fw1.x); t.y = f2tf(fw1.y); t.z = f2tf(fw1.z); t.w = f2tf(fw1.w);
            *(uint4*)&sB[sr][sc + 4] = t;
        }
        __syncthreads();

        // Prefetch next tile (overlaps with the MMA work below)
        if (kt < 63) {
            const int k0 = (kt + 1) * 16;
            fx0 = *(const float4*)(xp + k0);
            fx1 = *(const float4*)(xp + k0 + 4);
            fw0 = *(const float4*)(wp + k0);
            fw1 = *(const float4*)(wp + k0 + 4);
        }

        #pragma unroll
        for (int ks = 0; ks < 2; ks++) {
            const int k8 = ks * 8;
            uint32_t a[4][4], bf[4][2];
            #pragma unroll
            for (int mt = 0; mt < 4; mt++) {
                const int mrow = wm * 64 + mt * 16 + lg;
                a[mt][0] = sA[mrow][k8 + lt];
                a[mt][1] = sA[mrow + 8][k8 + lt];
                a[mt][2] = sA[mrow][k8 + lt + 4];
                a[mt][3] = sA[mrow + 8][k8 + lt + 4];
            }
            #pragma unroll
            for (int nt = 0; nt < 4; nt++) {
                const int ncol = wn * 32 + nt * 8 + lg;
                bf[nt][0] = sB[ncol][k8 + lt];
                bf[nt][1] = sB[ncol][k8 + lt + 4];
            }
            #pragma unroll
            for (int mt = 0; mt < 4; mt++)
                #pragma unroll
                for (int nt = 0; nt < 4; nt++)
                    mma8(c[mt][nt], a[mt][0], a[mt][1], a[mt][2], a[mt][3],
                         bf[nt][0], bf[nt][1]);
        }
    }

    // Epilogue: bias + scale, scatter to [B,H,S,D]
    #pragma unroll
    for (int nt = 0; nt < 4; nt++) {
        const int n = n0 + wn * 32 + nt * 8 + (lt << 1);
        const int h = n >> 6;
        const int d = n & 63;
        const float b0v = bias[n], b1v = bias[n + 1];
        #pragma unroll
        for (int mt = 0; mt < 4; mt++) {
            #pragma unroll
            for (int half = 0; half < 2; half++) {
                const int m  = m0 + wm * 64 + mt * 16 + lg + half * 8;
                const int bb = m >> 12;
                const int s  = m & (S_ - 1);
                float2 o;
                o.x = (c[mt][nt][half * 2 + 0] + b0v) * scale;
                o.y = (c[mt][nt][half * 2 + 1] + b1v) * scale;
                *(float2*)(outp + (((size_t)bb * H_ + h) * S_ + s) * D_ + d) = o;
            }
        }
    }
}

// ---------------------------------------------------------------------------
// Kernel 2: banded attention, tensor-core tf32 mma for QK^T and PV.
// (byte-for-byte the R9 version: 189us measured)
// ---------------------------------------------------------------------------
__global__ __launch_bounds__(128)
void banded_attn_tc(const int* __restrict__ amask, float* __restrict__ out)
{
    __shared__ uint32_t Ks[64][68];   // tf32, natural [key][d]
    __shared__ uint32_t Vs[64][72];   // tf32, natural [key][d]
    __shared__ float    am_s[64];     // additive mask per key of current tile

    const int q0 = blockIdx.x * 64;
    const int h  = blockIdx.y;
    const int b  = blockIdx.z;

    const int tid  = threadIdx.x;
    const int lane = tid & 31;
    const int wid  = tid >> 5;        // 0..3
    const int lg   = lane >> 2;       // 0..7
    const int lt   = lane & 3;        // 0..3

    const size_t head_off = (((size_t)b * H_ + h) * S_) * D_;
    const float* kb_ = g_k + head_off;
    const float* vb_ = g_v + head_off;

    const int qi0 = q0 + wid * 16 + lg;
    const int qi1 = qi0 + 8;
    const float* qr0 = g_q + head_off + (size_t)qi0 * D_;
    const float* qr1 = qr0 + 8 * D_;

    uint32_t qf[8][4];
    #pragma unroll
    for (int ks = 0; ks < 8; ks++) {
        qf[ks][0] = f2tf(qr0[ks * 8 + lt]);
        qf[ks][1] = f2tf(qr1[ks * 8 + lt]);
        qf[ks][2] = f2tf(qr0[ks * 8 + lt + 4]);
        qf[ks][3] = f2tf(qr1[ks * 8 + lt + 4]);
    }

    const int lo0 = max(0, qi0 - W_), hi0 = min(S_ - 1, qi0 + W_);
    const int lo1 = max(0, qi1 - W_), hi1 = min(S_ - 1, qi1 + W_);

    float m0r = -1e30f, m1r = -1e30f, l0 = 0.f, l1 = 0.f;
    float oacc[8][4];
    #pragma unroll
    for (int vn = 0; vn < 8; vn++)
        #pragma unroll
        for (int r = 0; r < 4; r++) oacc[vn][r] = 0.f;

    for (int t = 0; t < 9; t++) {
        const int kt0 = q0 - W_ + t * 64;
        if (kt0 + 63 < 0 || kt0 >= S_) continue;

        __syncthreads();

        #pragma unroll
        for (int it = 0; it < 8; it++) {
            int idx = tid + it * 128;
            int r   = idx >> 4;
            int d4  = (idx & 15) << 2;
            int jg  = kt0 + r;
            float4 kv = make_float4(0.f, 0.f, 0.f, 0.f);
            float4 vv = make_float4(0.f, 0.f, 0.f, 0.f);
            if (jg >= 0 && jg < S_) {
                kv = *(const float4*)(kb_ + (size_t)jg * D_ + d4);
                vv = *(const float4*)(vb_ + (size_t)jg * D_ + d4);
            }
            uint4 kt4, vt4;
            kt4.x = f2tf(kv.x); kt4.y = f2tf(kv.y); kt4.z = f2tf(kv.z); kt4.w = f2tf(kv.w);
            vt4.x = f2tf(vv.x); vt4.y = f2tf(vv.y); vt4.z = f2tf(vv.z); vt4.w = f2tf(vv.w);
            *(uint4*)&Ks[r][d4] = kt4;
            *(uint4*)&Vs[r][d4] = vt4;
        }
        if (tid < 64) {
            int jg = kt0 + tid;
            am_s[tid] = (jg >= 0 && jg < S_ && amask[b * S_ + jg] != 0) ? -10000.f : 0.f;
        }
        __syncthreads();

        float s[8][4];
        #pragma unroll
        for (int nt = 0; nt < 8; nt++)
            #pragma unroll
            for (int r = 0; r < 4; r++) s[nt][r] = 0.f;

        #pragma unroll
        for (int ks = 0; ks < 8; ks++) {
            const int k8 = ks * 8;
            #pragma unroll
            for (int nt = 0; nt < 8; nt++) {
                uint32_t b0 = Ks[nt * 8 + lg][k8 + lt];
                uint32_t b1 = Ks[nt * 8 + lg][k8 + lt + 4];
                mma8(s[nt], qf[ks][0], qf[ks][1], qf[ks][2], qf[ks][3], b0, b1);
            }
        }

        float tmax0 = -1e30f, tmax1 = -1e30f;
        #pragma unroll
        for (int nt = 0; nt < 8; nt++) {
            const int c0  = (nt << 3) + (lt << 1);
            const int jg0 = kt0 + c0, jg1 = jg0 + 1;
            const float am0 = am_s[c0], am1 = am_s[c0 + 1];
            s[nt][0] = (jg0 >= lo0 && jg0 <= hi0) ? s[nt][0] + am0 : -1e30f;
            s[nt][1] = (jg1 >= lo0 && jg1 <= hi0) ? s[nt][1] + am1 : -1e30f;
            s[nt][2] = (jg0 >= lo1 && jg0 <= hi1) ? s[nt][2] + am0 : -1e30f;
            s[nt][3] = (jg1 >= lo1 && jg1 <= hi1) ? s[nt][3] + am1 : -1e30f;
            tmax0 = fmaxf(tmax0, fmaxf(s[nt][0], s[nt][1]));
            tmax1 = fmaxf(tmax1, fmaxf(s[nt][2], s[nt][3]));
        }
        tmax0 = fmaxf(tmax0, __shfl_xor_sync(0xffffffffu, tmax0, 1, 32));
        tmax0 = fmaxf(tmax0, __shfl_xor_sync(0xffffffffu, tmax0, 2, 32));
        tmax1 = fmaxf(tmax1, __shfl_xor_sync(0xffffffffu, tmax1, 1, 32));
        tmax1 = fmaxf(tmax1, __shfl_xor_sync(0xffffffffu, tmax1, 2, 32));

        const float mn0 = fmaxf(m0r, tmax0), mn1 = fmaxf(m1r, tmax1);
        const float corr0 = __expf(m0r - mn0), corr1 = __expf(m1r - mn1);

        float rs0 = 0.f, rs1 = 0.f;
        #pragma unroll
        for (int nt = 0; nt < 8; nt++) {
            float e0 = (s[nt][0] > -1e29f) ? __expf(s[nt][0] - mn0) : 0.f;
            float e1 = (s[nt][1] > -1e29f) ? __expf(s[nt][1] - mn0) : 0.f;
            float e2 = (s[nt][2] > -1e29f) ? __expf(s[nt][2] - mn1) : 0.f;
            float e3 = (s[nt][3] > -1e29f) ? __expf(s[nt][3] - mn1) : 0.f;
            s[nt][0] = e0; s[nt][1] = e1; s[nt][2] = e2; s[nt][3] = e3;
            rs0 += e0 + e1; rs1 += e2 + e3;
        }
        rs0 += __shfl_xor_sync(0xffffffffu, rs0, 1, 32);
        rs0 += __shfl_xor_sync(0xffffffffu, rs0, 2, 32);
        rs1 += __shfl_xor_sync(0xffffffffu, rs1, 1, 32);
        rs1 += __shfl_xor_sync(0xffffffffu, rs1, 2, 32);

        l0 = l0 * corr0 + rs0; m0r = mn0;
        l1 = l1 * corr1 + rs1; m1r = mn1;
        #pragma unroll
        for (int vn = 0; vn < 8; vn++) {
            oacc[vn][0] *= corr0; oacc[vn][1] *= corr0;
            oacc[vn][2] *= corr1; oacc[vn][3] *= corr1;
        }

        const int s0l = (lg << 2) + (lt >> 1);
        const int s1l = s0l + 2;
        const bool odd = (lt & 1);
        #pragma unroll
        for (int kk = 0; kk < 8; kk++) {
            float t00 = __shfl_sync(0xffffffffu, s[kk][0], s0l, 32);
            float t01 = __shfl_sync(0xffffffffu, s[kk][1], s0l, 32);
            float t10 = __shfl_sync(0xffffffffu, s[kk][2], s0l, 32);
            float t11 = __shfl_sync(0xffffffffu, s[kk][3], s0l, 32);
            float t20 = __shfl_sync(0xffffffffu, s[kk][0], s1l, 32);
            float t21 = __shfl_sync(0xffffffffu, s[kk][1], s1l, 32);
            float t30 = __shfl_sync(0xffffffffu, s[kk][2], s1l, 32);
            float t31 = __shfl_sync(0xffffffffu, s[kk][3], s1l, 32);
            uint32_t a0 = f2tf(odd ? t01 : t00);
            uint32_t a1 = f2tf(odd ? t11 : t10);
            uint32_t a2 = f2tf(odd ? t21 : t20);
            uint32_t a3 = f2tf(odd ? t31 : t30);
            const int k8 = kk * 8;
            #pragma unroll
            for (int vn = 0; vn < 8; vn++) {
                uint32_t b0 = Vs[k8 + lt][vn * 8 + lg];
                uint32_t b1 = Vs[k8 + lt + 4][vn * 8 + lg];
                mma8(oacc[vn], a0, a1, a2, a3, b0, b1);
            }
        }
    }

    const float inv0 = 1.f / l0, inv1 = 1.f / l1;
    float* o0 = out + ((size_t)b * S_ + qi0) * E_ + h * D_;
    float* o1 = out + ((size_t)b * S_ + qi1) * E_ + h * D_;
    #pragma unroll
    for (int vn = 0; vn < 8; vn++) {
        const int col = vn * 8 + (lt << 1);
        float2 r0, r1;
        r0.x = oacc[vn][0] * inv0; r0.y = oacc[vn][1] * inv0;
        r1.x = oacc[vn][2] * inv1; r1.y = oacc[vn][3] * inv1;
        *(float2*)(o0 + col) = r0;
        *(float2*)(o1 + col) = r1;
    }
}

// ---------------------------------------------------------------------------
extern "C" void kernel_launch(void* const* d_in, const int* in_sizes, int n_in,
                              void* d_out, int out_size)
{
    const float* hs    = (const float*)d_in[0];   // [B,S,E]
    const int*   amask = (const int*)  d_in[1];   // [B,S]
    const float* qw    = (const float*)d_in[2];
    const float* qb    = (const float*)d_in[3];
    const float* kw    = (const float*)d_in[4];
    const float* kb    = (const float*)d_in[5];
    const float* vw    = (const float*)d_in[6];
    const float* vb    = (const float*)d_in[7];
    float* out = (float*)d_out;

    dim3 g1((B_ * S_) / 128, E_ / 128, 3);   // 64 x 8 x 3
    qkv_gemm_tf32<<<g1, 256>>>(hs, qw, qb, kw, kb, vw, vb);

    dim3 g2(S_ / 64, H_, B_);                // 64 x 16 x 2
    banded_attn_tc<<<g2, 128>>>(amask, out);
}

// round 15
// speedup vs baseline: 1.7848x; 1.2920x over previous
#include <cuda_runtime.h>
#include <cuda_fp16.h>
#include <cstdint>

#define B_ 2
#define S_ 4096
#define E_ 1024
#define H_ 16
#define D_ 64
#define W_ 256

// Scratch: q/k/v in [B,H,S,D] layout (static device arrays — no allocs)
__device__ float g_q[(size_t)B_ * H_ * S_ * D_];
__device__ float g_k[(size_t)B_ * H_ * S_ * D_];
__device__ float g_v[(size_t)B_ * H_ * S_ * D_];

// ---------------------------------------------------------------------------
// helpers
// ---------------------------------------------------------------------------
__device__ __forceinline__ uint32_t f2tf(float x) {
    uint32_t r;
    asm("cvt.rna.tf32.f32 %0, %1;" : "=r"(r) : "f"(x));
    return r;
}

// tf32 m16n8k8 (attention kernel)
__device__ __forceinline__ void mma8(float c[4],
                                     uint32_t a0, uint32_t a1, uint32_t a2, uint32_t a3,
                                     uint32_t b0, uint32_t b1) {
    asm volatile(
        "mma.sync.aligned.m16n8k8.row.col.f32.tf32.tf32.f32 "
        "{%0,%1,%2,%3}, {%4,%5,%6,%7}, {%8,%9}, {%0,%1,%2,%3};"
        : "+f"(c[0]), "+f"(c[1]), "+f"(c[2]), "+f"(c[3])
        : "r"(a0), "r"(a1), "r"(a2), "r"(a3), "r"(b0), "r"(b1));
}

// fp16 m16n8k16, fp32 accumulate (GEMM kernel)
__device__ __forceinline__ void mma16h(float c[4],
                                       uint32_t a0, uint32_t a1, uint32_t a2, uint32_t a3,
                                       uint32_t b0, uint32_t b1) {
    asm volatile(
        "mma.sync.aligned.m16n8k16.row.col.f32.f16.f16.f32 "
        "{%0,%1,%2,%3}, {%4,%5,%6,%7}, {%8,%9}, {%0,%1,%2,%3};"
        : "+f"(c[0]), "+f"(c[1]), "+f"(c[2]), "+f"(c[3])
        : "r"(a0), "r"(a1), "r"(a2), "r"(a3), "r"(b0), "r"(b1));
}

__device__ __forceinline__ uint32_t pack_h2(float lo, float hi) {
    __half2 h = __floats2half2_rn(lo, hi);
    return *(uint32_t*)&h;
}

// ---------------------------------------------------------------------------
// Kernel 1: fused QKV projection, fp16 tensor-core MMA (fp32 accumulate).
// C[M=8192,N=1024] = X @ W^T + b (q additionally * 1/8), scattered to [B,H,S,D].
// Block 256 threads (8 warps), tile 128x128, BK=16 (one k16 mma step/iter),
// single-buffered with register prefetch.
// Smem [row][k-half2-word], stride 12 words: fragment LDS bank =
// (12*lg + lt) mod 32 = all 32 banks distinct -> conflict-free.
// Per block-iter smem traffic: 24KB reads + 8KB writes (half the tf32 version).
// ---------------------------------------------------------------------------
__global__ __launch_bounds__(256, 2)
void qkv_gemm_fp16(const float* __restrict__ X,
                   const float* __restrict__ Wq, const float* __restrict__ bq,
                   const float* __restrict__ Wk, const float* __restrict__ bk,
                   const float* __restrict__ Wv, const float* __restrict__ bv)
{
    const float* Wt; const float* bias; float* outp; float scale;
    if (blockIdx.z == 0)      { Wt = Wq; bias = bq; outp = g_q; scale = 0.125f; }
    else if (blockIdx.z == 1) { Wt = Wk; bias = bk; outp = g_k; scale = 1.0f;   }
    else                      { Wt = Wv; bias = bv; outp = g_v; scale = 1.0f;   }

    __shared__ uint32_t sA[128][12];   // [m][k-word] half2, 8 words data + 4 pad
    __shared__ uint32_t sB[128][12];   // [n][k-word] half2

    const int m0   = blockIdx.x * 128;
    const int n0   = blockIdx.y * 128;
    const int tid  = threadIdx.x;
    const int lane = tid & 31;
    const int wid  = tid >> 5;
    const int wm   = wid & 1;          // 64-row band
    const int wn   = wid >> 1;         // 32-col band
    const int lg   = lane >> 2;        // 0..7
    const int lt   = lane & 3;         // 0..3

    // staging: thread covers row sr, 8 floats starting at fc (two float4)
    const int sr = tid >> 1;           // 0..127
    const int fc = (tid & 1) << 3;     // 0 or 8 (float offset)
    const int wc = (tid & 1) << 2;     // 0 or 4 (half2-word offset)

    const float* xp = X  + (size_t)(m0 + sr) * E_ + fc;
    const float* wp = Wt + (size_t)(n0 + sr) * E_ + fc;

    float c[4][4][4];
    #pragma unroll
    for (int i = 0; i < 4; i++)
        #pragma unroll
        for (int j = 0; j < 4; j++)
            #pragma unroll
            for (int r = 0; r < 4; r++) c[i][j][r] = 0.f;

    // Prefetch first K-tile into registers
    float4 fx0 = *(const float4*)(xp);
    float4 fx1 = *(const float4*)(xp + 4);
    float4 fw0 = *(const float4*)(wp);
    float4 fw1 = *(const float4*)(wp + 4);

    for (int kt = 0; kt < 64; kt++) {
        __syncthreads();   // previous tile's fragment reads complete
        {
            uint4 t;
            t.x = pack_h2(fx0.x, fx0.y); t.y = pack_h2(fx0.z, fx0.w);
            t.z = pack_h2(fx1.x, fx1.y); t.w = pack_h2(fx1.z, fx1.w);
            *(uint4*)&sA[sr][wc] = t;
            t.x = pack_h2(fw0.x, fw0.y); t.y = pack_h2(fw0.z, fw0.w);
            t.z = pack_h2(fw1.x, fw1.y); t.w = pack_h2(fw1.z, fw1.w);
            *(uint4*)&sB[sr][wc] = t;
        }
        __syncthreads();

        // Prefetch next tile (overlaps with the MMA work below)
        if (kt < 63) {
            const int k0 = (kt + 1) * 16;
            fx0 = *(const float4*)(xp + k0);
            fx1 = *(const float4*)(xp + k0 + 4);
            fw0 = *(const float4*)(wp + k0);
            fw1 = *(const float4*)(wp + k0 + 4);
        }

        // one m16n8k16 k-step per tile
        uint32_t a[4][4], bf[4][2];
        #pragma unroll
        for (int mt = 0; mt < 4; mt++) {
            const int mrow = wm * 64 + mt * 16 + lg;
            a[mt][0] = sA[mrow][lt];           // (row lg,   k 2lt..2lt+1)
            a[mt][1] = sA[mrow + 8][lt];       // (row lg+8, k 2lt..2lt+1)
            a[mt][2] = sA[mrow][lt + 4];       // (row lg,   k 2lt+8..2lt+9)
            a[mt][3] = sA[mrow + 8][lt + 4];   // (row lg+8, k 2lt+8..2lt+9)
        }
        #pragma unroll
        for (int nt = 0; nt < 4; nt++) {
            const int ncol = wn * 32 + nt * 8 + lg;
            bf[nt][0] = sB[ncol][lt];          // (k 2lt..2lt+1,   n lg)
            bf[nt][1] = sB[ncol][lt + 4];      // (k 2lt+8..2lt+9, n lg)
        }
        #pragma unroll
        for (int mt = 0; mt < 4; mt++)
            #pragma unroll
            for (int nt = 0; nt < 4; nt++)
                mma16h(c[mt][nt], a[mt][0], a[mt][1], a[mt][2], a[mt][3],
                       bf[nt][0], bf[nt][1]);
    }

    // Epilogue: bias + scale (fp32), scatter to [B,H,S,D]
    #pragma unroll
    for (int nt = 0; nt < 4; nt++) {
        const int n = n0 + wn * 32 + nt * 8 + (lt << 1);
        const int h = n >> 6;
        const int d = n & 63;
        const float b0v = bias[n], b1v = bias[n + 1];
        #pragma unroll
        for (int mt = 0; mt < 4; mt++) {
            #pragma unroll
            for (int half = 0; half < 2; half++) {
                const int m  = m0 + wm * 64 + mt * 16 + lg + half * 8;
                const int bb = m >> 12;
                const int s  = m & (S_ - 1);
                float2 o;
                o.x = (c[mt][nt][half * 2 + 0] + b0v) * scale;
                o.y = (c[mt][nt][half * 2 + 1] + b1v) * scale;
                *(float2*)(outp + (((size_t)bb * H_ + h) * S_ + s) * D_ + d) = o;
            }
        }
    }
}

// ---------------------------------------------------------------------------
// Kernel 2: banded attention, tensor-core tf32 mma for QK^T and PV.
// (byte-for-byte the measured-good R9 version: ~192us)
// ---------------------------------------------------------------------------
__global__ __launch_bounds__(128)
void banded_attn_tc(const int* __restrict__ amask, float* __restrict__ out)
{
    __shared__ uint32_t Ks[64][68];   // tf32, natural [key][d]
    __shared__ uint32_t Vs[64][72];   // tf32, natural [key][d]
    __shared__ float    am_s[64];     // additive mask per key of current tile

    const int q0 = blockIdx.x * 64;
    const int h  = blockIdx.y;
    const int b  = blockIdx.z;

    const int tid  = threadIdx.x;
    const int lane = tid & 31;
    const int wid  = tid >> 5;        // 0..3
    const int lg   = lane >> 2;       // 0..7
    const int lt   = lane & 3;        // 0..3

    const size_t head_off = (((size_t)b * H_ + h) * S_) * D_;
    const float* kb_ = g_k + head_off;
    const float* vb_ = g_v + head_off;

    const int qi0 = q0 + wid * 16 + lg;
    const int qi1 = qi0 + 8;
    const float* qr0 = g_q + head_off + (size_t)qi0 * D_;
    const float* qr1 = qr0 + 8 * D_;

    uint32_t qf[8][4];
    #pragma unroll
    for (int ks = 0; ks < 8; ks++) {
        qf[ks][0] = f2tf(qr0[ks * 8 + lt]);
        qf[ks][1] = f2tf(qr1[ks * 8 + lt]);
        qf[ks][2] = f2tf(qr0[ks * 8 + lt + 4]);
        qf[ks][3] = f2tf(qr1[ks * 8 + lt + 4]);
    }

    const int lo0 = max(0, qi0 - W_), hi0 = min(S_ - 1, qi0 + W_);
    const int lo1 = max(0, qi1 - W_), hi1 = min(S_ - 1, qi1 + W_);

    float m0r = -1e30f, m1r = -1e30f, l0 = 0.f, l1 = 0.f;
    float oacc[8][4];
    #pragma unroll
    for (int vn = 0; vn < 8; vn++)
        #pragma unroll
        for (int r = 0; r < 4; r++) oacc[vn][r] = 0.f;

    for (int t = 0; t < 9; t++) {
        const int kt0 = q0 - W_ + t * 64;
        if (kt0 + 63 < 0 || kt0 >= S_) continue;

        __syncthreads();

        #pragma unroll
        for (int it = 0; it < 8; it++) {
            int idx = tid + it * 128;
            int r   = idx >> 4;
            int d4  = (idx & 15) << 2;
            int jg  = kt0 + r;
            float4 kv = make_float4(0.f, 0.f, 0.f, 0.f);
            float4 vv = make_float4(0.f, 0.f, 0.f, 0.f);
            if (jg >= 0 && jg < S_) {
                kv = *(const float4*)(kb_ + (size_t)jg * D_ + d4);
                vv = *(const float4*)(vb_ + (size_t)jg * D_ + d4);
            }
            uint4 kt4, vt4;
            kt4.x = f2tf(kv.x); kt4.y = f2tf(kv.y); kt4.z = f2tf(kv.z); kt4.w = f2tf(kv.w);
            vt4.x = f2tf(vv.x); vt4.y = f2tf(vv.y); vt4.z = f2tf(vv.z); vt4.w = f2tf(vv.w);
            *(uint4*)&Ks[r][d4] = kt4;
            *(uint4*)&Vs[r][d4] = vt4;
        }
        if (tid < 64) {
            int jg = kt0 + tid;
            am_s[tid] = (jg >= 0 && jg < S_ && amask[b * S_ + jg] != 0) ? -10000.f : 0.f;
        }
        __syncthreads();

        float s[8][4];
        #pragma unroll
        for (int nt = 0; nt < 8; nt++)
            #pragma unroll
            for (int r = 0; r < 4; r++) s[nt][r] = 0.f;

        #pragma unroll
        for (int ks = 0; ks < 8; ks++) {
            const int k8 = ks * 8;
            #pragma unroll
            for (int nt = 0; nt < 8; nt++) {
                uint32_t b0 = Ks[nt * 8 + lg][k8 + lt];
                uint32_t b1 = Ks[nt * 8 + lg][k8 + lt + 4];
                mma8(s[nt], qf[ks][0], qf[ks][1], qf[ks][2], qf[ks][3], b0, b1);
            }
        }

        float tmax0 = -1e30f, tmax1 = -1e30f;
        #pragma unroll
        for (int nt = 0; nt < 8; nt++) {
            const int c0  = (nt << 3) + (lt << 1);
            const int jg0 = kt0 + c0, jg1 = jg0 + 1;
            const float am0 = am_s[c0], am1 = am_s[c0 + 1];
            s[nt][0] = (jg0 >= lo0 && jg0 <= hi0) ? s[nt][0] + am0 : -1e30f;
            s[nt][1] = (jg1 >= lo0 && jg1 <= hi0) ? s[nt][1] + am1 : -1e30f;
            s[nt][2] = (jg0 >= lo1 && jg0 <= hi1) ? s[nt][2] + am0 : -1e30f;
            s[nt][3] = (jg1 >= lo1 && jg1 <= hi1) ? s[nt][3] + am1 : -1e30f;
            tmax0 = fmaxf(tmax0, fmaxf(s[nt][0], s[nt][1]));
            tmax1 = fmaxf(tmax1, fmaxf(s[nt][2], s[nt][3]));
        }
        tmax0 = fmaxf(tmax0, __shfl_xor_sync(0xffffffffu, tmax0, 1, 32));
        tmax0 = fmaxf(tmax0, __shfl_xor_sync(0xffffffffu, tmax0, 2, 32));
        tmax1 = fmaxf(tmax1, __shfl_xor_sync(0xffffffffu, tmax1, 1, 32));
        tmax1 = fmaxf(tmax1, __shfl_xor_sync(0xffffffffu, tmax1, 2, 32));

        const float mn0 = fmaxf(m0r, tmax0), mn1 = fmaxf(m1r, tmax1);
        const float corr0 = __expf(m0r - mn0), corr1 = __expf(m1r - mn1);

        float rs0 = 0.f, rs1 = 0.f;
        #pragma unroll
        for (int nt = 0; nt < 8; nt++) {
            float e0 = (s[nt][0] > -1e29f) ? __expf(s[nt][0] - mn0) : 0.f;
            float e1 = (s[nt][1] > -1e29f) ? __expf(s[nt][1] - mn0) : 0.f;
            float e2 = (s[nt][2] > -1e29f) ? __expf(s[nt][2] - mn1) : 0.f;
            float e3 = (s[nt][3] > -1e29f) ? __expf(s[nt][3] - mn1) : 0.f;
            s[nt][0] = e0; s[nt][1] = e1; s[nt][2] = e2; s[nt][3] = e3;
            rs0 += e0 + e1; rs1 += e2 + e3;
        }
        rs0 += __shfl_xor_sync(0xffffffffu, rs0, 1, 32);
        rs0 += __shfl_xor_sync(0xffffffffu, rs0, 2, 32);
        rs1 += __shfl_xor_sync(0xffffffffu, rs1, 1, 32);
        rs1 += __shfl_xor_sync(0xffffffffu, rs1, 2, 32);

        l0 = l0 * corr0 + rs0; m0r = mn0;
        l1 = l1 * corr1 + rs1; m1r = mn1;
        #pragma unroll
        for (int vn = 0; vn < 8; vn++) {
            oacc[vn][0] *= corr0; oacc[vn][1] *= corr0;
            oacc[vn][2] *= corr1; oacc[vn][3] *= corr1;
        }

        const int s0l = (lg << 2) + (lt >> 1);
        const int s1l = s0l + 2;
        const bool odd = (lt & 1);
        #pragma unroll
        for (int kk = 0; kk < 8; kk++) {
            float t00 = __shfl_sync(0xffffffffu, s[kk][0], s0l, 32);
            float t01 = __shfl_sync(0xffffffffu, s[kk][1], s0l, 32);
            float t10 = __shfl_sync(0xffffffffu, s[kk][2], s0l, 32);
            float t11 = __shfl_sync(0xffffffffu, s[kk][3], s0l, 32);
            float t20 = __shfl_sync(0xffffffffu, s[kk][0], s1l, 32);
            float t21 = __shfl_sync(0xffffffffu, s[kk][1], s1l, 32);
            float t30 = __shfl_sync(0xffffffffu, s[kk][2], s1l, 32);
            float t31 = __shfl_sync(0xffffffffu, s[kk][3], s1l, 32);
            uint32_t a0 = f2tf(odd ? t01 : t00);
            uint32_t a1 = f2tf(odd ? t11 : t10);
            uint32_t a2 = f2tf(odd ? t21 : t20);
            uint32_t a3 = f2tf(odd ? t31 : t30);
            const int k8 = kk * 8;
            #pragma unroll
            for (int vn = 0; vn < 8; vn++) {
                uint32_t b0 = Vs[k8 + lt][vn * 8 + lg];
                uint32_t b1 = Vs[k8 + lt + 4][vn * 8 + lg];
                mma8(oacc[vn], a0, a1, a2, a3, b0, b1);
            }
        }
    }

    const float inv0 = 1.f / l0, inv1 = 1.f / l1;
    float* o0 = out + ((size_t)b * S_ + qi0) * E_ + h * D_;
    float* o1 = out + ((size_t)b * S_ + qi1) * E_ + h * D_;
    #pragma unroll
    for (int vn = 0; vn < 8; vn++) {
        const int col = vn * 8 + (lt << 1);
        float2 r0, r1;
        r0.x = oacc[vn][0] * inv0; r0.y = oacc[vn][1] * inv0;
        r1.x = oacc[vn][2] * inv1; r1.y = oacc[vn][3] * inv1;
        *(float2*)(o0 + col) = r0;
        *(float2*)(o1 + col) = r1;
    }
}

// ---------------------------------------------------------------------------
extern "C" void kernel_launch(void* const* d_in, const int* in_sizes, int n_in,
                              void* d_out, int out_size)
{
    const float* hs    = (const float*)d_in[0];   // [B,S,E]
    const int*   amask = (const int*)  d_in[1];   // [B,S]
    const float* qw    = (const float*)d_in[2];
    const float* qb    = (const float*)d_in[3];
    const float* kw    = (const float*)d_in[4];
    const float* kb    = (const float*)d_in[5];
    const float* vw    = (const float*)d_in[6];
    const float* vb    = (const float*)d_in[7];
    float* out = (float*)d_out;

    dim3 g1((B_ * S_) / 128, E_ / 128, 3);   // 64 x 8 x 3
    qkv_gemm_fp16<<<g1, 256>>>(hs, qw, qb, kw, kb, vw, vb);

    dim3 g2(S_ / 64, H_, B_);                // 64 x 16 x 2
    banded_attn_tc<<<g2, 128>>>(amask, out);
}

// round 17
// speedup vs baseline: 2.2205x; 1.2441x over previous
#include <cuda_runtime.h>
#include <cuda_fp16.h>
#include <cstdint>

#define B_ 2
#define S_ 4096
#define E_ 1024
#define H_ 16
#define D_ 64
#define W_ 256

// Scratch: q/k/v in [B,H,S,D] layout (static device arrays — no allocs)
__device__ float g_q[(size_t)B_ * H_ * S_ * D_];
__device__ float g_k[(size_t)B_ * H_ * S_ * D_];
__device__ float g_v[(size_t)B_ * H_ * S_ * D_];
// fp16 (half2-packed) copies of X and the three weight matrices
__device__ uint32_t g_xh[(size_t)B_ * S_ * E_ / 2];   // [8192][512] half2 words
__device__ uint32_t g_wqh[(size_t)E_ * E_ / 2];
__device__ uint32_t g_wkh[(size_t)E_ * E_ / 2];
__device__ uint32_t g_wvh[(size_t)E_ * E_ / 2];

// ---------------------------------------------------------------------------
// helpers
// ---------------------------------------------------------------------------
__device__ __forceinline__ uint32_t f2tf(float x) {
    uint32_t r;
    asm("cvt.rna.tf32.f32 %0, %1;" : "=r"(r) : "f"(x));
    return r;
}

// tf32 m16n8k8 (attention kernel)
__device__ __forceinline__ void mma8(float c[4],
                                     uint32_t a0, uint32_t a1, uint32_t a2, uint32_t a3,
                                     uint32_t b0, uint32_t b1) {
    asm volatile(
        "mma.sync.aligned.m16n8k8.row.col.f32.tf32.tf32.f32 "
        "{%0,%1,%2,%3}, {%4,%5,%6,%7}, {%8,%9}, {%0,%1,%2,%3};"
        : "+f"(c[0]), "+f"(c[1]), "+f"(c[2]), "+f"(c[3])
        : "r"(a0), "r"(a1), "r"(a2), "r"(a3), "r"(b0), "r"(b1));
}

// fp16 m16n8k16, fp32 accumulate (GEMM kernel)
__device__ __forceinline__ void mma16h(float c[4],
                                       uint32_t a0, uint32_t a1, uint32_t a2, uint32_t a3,
                                       uint32_t b0, uint32_t b1) {
    asm volatile(
        "mma.sync.aligned.m16n8k16.row.col.f32.f16.f16.f32 "
        "{%0,%1,%2,%3}, {%4,%5,%6,%7}, {%8,%9}, {%0,%1,%2,%3};"
        : "+f"(c[0]), "+f"(c[1]), "+f"(c[2]), "+f"(c[3])
        : "r"(a0), "r"(a1), "r"(a2), "r"(a3), "r"(b0), "r"(b1));
}

__device__ __forceinline__ uint32_t pack_h2(float lo, float hi) {
    __half2 h = __floats2half2_rn(lo, hi);
    return *(uint32_t*)&h;
}

// ---------------------------------------------------------------------------
// Kernel 0: fp32 -> fp16(rn) pre-conversion (4 floats -> 2 half2 words/thread).
// Same __floats2half2_rn rounding as the R14 in-loop pack: values bit-identical.
// ---------------------------------------------------------------------------
__global__ __launch_bounds__(256)
void conv_fp16(const float* __restrict__ src, uint32_t* __restrict__ dst, int n4)
{
    int i = blockIdx.x * 256 + threadIdx.x;
    if (i < n4) {
        float4 v = ((const float4*)src)[i];
        uint2 o;
        o.x = pack_h2(v.x, v.y);
        o.y = pack_h2(v.z, v.w);
        ((uint2*)dst)[i] = o;
    }
}

// ---------------------------------------------------------------------------
// Kernel 1: fused QKV projection, fp16 tensor-core MMA (fp32 accumulate).
// Identical mainloop structure to the measured R14 kernel; only the gmem
// operands are now pre-packed fp16 (half the bytes, no in-loop cvt).
// Block 256 threads (8 warps), tile 128x128, BK=16, single-buffered with
// register prefetch. Smem [row][k-word] stride 12: conflict-free LDS.
// ---------------------------------------------------------------------------
__global__ __launch_bounds__(256, 2)
void qkv_gemm_fp16(const float* __restrict__ bq,
                   const float* __restrict__ bk,
                   const float* __restrict__ bv)
{
    const uint32_t* Wh; const float* bias; float* outp; float scale;
    if (blockIdx.z == 0)      { Wh = g_wqh; bias = bq; outp = g_q; scale = 0.125f; }
    else if (blockIdx.z == 1) { Wh = g_wkh; bias = bk; outp = g_k; scale = 1.0f;   }
    else                      { Wh = g_wvh; bias = bv; outp = g_v; scale = 1.0f;   }

    __shared__ uint32_t sA[128][12];   // [m][k-word] half2, 8 words data + 4 pad
    __shared__ uint32_t sB[128][12];   // [n][k-word] half2

    const int m0   = blockIdx.x * 128;
    const int n0   = blockIdx.y * 128;
    const int tid  = threadIdx.x;
    const int lane = tid & 31;
    const int wid  = tid >> 5;
    const int wm   = wid & 1;          // 64-row band
    const int wn   = wid >> 1;         // 32-col band
    const int lg   = lane >> 2;        // 0..7
    const int lt   = lane & 3;         // 0..3

    // staging: thread covers row sr, half2-words wc..wc+3 of the 8-word tile row
    const int sr = tid >> 1;           // 0..127
    const int wc = (tid & 1) << 2;     // 0 or 4 (word offset)

    const uint32_t* xp = g_xh + (size_t)(m0 + sr) * (E_ / 2) + wc;
    const uint32_t* wp = Wh   + (size_t)(n0 + sr) * (E_ / 2) + wc;

    float c[4][4][4];
    #pragma unroll
    for (int i = 0; i < 4; i++)
        #pragma unroll
        for (int j = 0; j < 4; j++)
            #pragma unroll
            for (int r = 0; r < 4; r++) c[i][j][r] = 0.f;

    // Prefetch first K-tile into registers (16 B per matrix per thread)
    uint4 fx = *(const uint4*)(xp);
    uint4 fw = *(const uint4*)(wp);

    for (int kt = 0; kt < 64; kt++) {
        __syncthreads();   // previous tile's fragment reads complete
        *(uint4*)&sA[sr][wc] = fx;
        *(uint4*)&sB[sr][wc] = fw;
        __syncthreads();

        // Prefetch next tile (overlaps with the MMA work below)
        if (kt < 63) {
            const int k0 = (kt + 1) * 8;   // 8 words = 16 halfs per k-tile
            fx = *(const uint4*)(xp + k0);
            fw = *(const uint4*)(wp + k0);
        }

        // one m16n8k16 k-step per tile
        uint32_t a[4][4], bf[4][2];
        #pragma unroll
        for (int mt = 0; mt < 4; mt++) {
            const int mrow = wm * 64 + mt * 16 + lg;
            a[mt][0] = sA[mrow][lt];           // (row lg,   k 2lt..2lt+1)
            a[mt][1] = sA[mrow + 8][lt];       // (row lg+8, k 2lt..2lt+1)
            a[mt][2] = sA[mrow][lt + 4];       // (row lg,   k 2lt+8..2lt+9)
            a[mt][3] = sA[mrow + 8][lt + 4];   // (row lg+8, k 2lt+8..2lt+9)
        }
        #pragma unroll
        for (int nt = 0; nt < 4; nt++) {
            const int ncol = wn * 32 + nt * 8 + lg;
            bf[nt][0] = sB[ncol][lt];          // (k 2lt..2lt+1,   n lg)
            bf[nt][1] = sB[ncol][lt + 4];      // (k 2lt+8..2lt+9, n lg)
        }
        #pragma unroll
        for (int mt = 0; mt < 4; mt++)
            #pragma unroll
            for (int nt = 0; nt < 4; nt++)
                mma16h(c[mt][nt], a[mt][0], a[mt][1], a[mt][2], a[mt][3],
                       bf[nt][0], bf[nt][1]);
    }

    // Epilogue: bias + scale (fp32), scatter to [B,H,S,D]
    #pragma unroll
    for (int nt = 0; nt < 4; nt++) {
        const int n = n0 + wn * 32 + nt * 8 + (lt << 1);
        const int h = n >> 6;
        const int d = n & 63;
        const float b0v = bias[n], b1v = bias[n + 1];
        #pragma unroll
        for (int mt = 0; mt < 4; mt++) {
            #pragma unroll
            for (int half = 0; half < 2; half++) {
                const int m  = m0 + wm * 64 + mt * 16 + lg + half * 8;
                const int bb = m >> 12;
                const int s  = m & (S_ - 1);
                float2 o;
                o.x = (c[mt][nt][half * 2 + 0] + b0v) * scale;
                o.y = (c[mt][nt][half * 2 + 1] + b1v) * scale;
                *(float2*)(outp + (((size_t)bb * H_ + h) * S_ + s) * D_ + d) = o;
            }
        }
    }
}

// ---------------------------------------------------------------------------
// Kernel 2: banded attention, tensor-core tf32 mma for QK^T and PV.
// (byte-for-byte the measured-good version: ~190us)
// ---------------------------------------------------------------------------
__global__ __launch_bounds__(128)
void banded_attn_tc(const int* __restrict__ amask, float* __restrict__ out)
{
    __shared__ uint32_t Ks[64][68];   // tf32, natural [key][d]
    __shared__ uint32_t Vs[64][72];   // tf32, natural [key][d]
    __shared__ float    am_s[64];     // additive mask per key of current tile

    const int q0 = blockIdx.x * 64;
    const int h  = blockIdx.y;
    const int b  = blockIdx.z;

    const int tid  = threadIdx.x;
    const int lane = tid & 31;
    const int wid  = tid >> 5;        // 0..3
    const int lg   = lane >> 2;       // 0..7
    const int lt   = lane & 3;        // 0..3

    const size_t head_off = (((size_t)b * H_ + h) * S_) * D_;
    const float* kb_ = g_k + head_off;
    const float* vb_ = g_v + head_off;

    const int qi0 = q0 + wid * 16 + lg;
    const int qi1 = qi0 + 8;
    const float* qr0 = g_q + head_off + (size_t)qi0 * D_;
    const float* qr1 = qr0 + 8 * D_;

    uint32_t qf[8][4];
    #pragma unroll
    for (int ks = 0; ks < 8; ks++) {
        qf[ks][0] = f2tf(qr0[ks * 8 + lt]);
        qf[ks][1] = f2tf(qr1[ks * 8 + lt]);
        qf[ks][2] = f2tf(qr0[ks * 8 + lt + 4]);
        qf[ks][3] = f2tf(qr1[ks * 8 + lt + 4]);
    }

    const int lo0 = max(0, qi0 - W_), hi0 = min(S_ - 1, qi0 + W_);
    const int lo1 = max(0, qi1 - W_), hi1 = min(S_ - 1, qi1 + W_);

    float m0r = -1e30f, m1r = -1e30f, l0 = 0.f, l1 = 0.f;
    float oacc[8][4];
    #pragma unroll
    for (int vn = 0; vn < 8; vn++)
        #pragma unroll
        for (int r = 0; r < 4; r++) oacc[vn][r] = 0.f;

    for (int t = 0; t < 9; t++) {
        const int kt0 = q0 - W_ + t * 64;
        if (kt0 + 63 < 0 || kt0 >= S_) continue;

        __syncthreads();

        #pragma unroll
        for (int it = 0; it < 8; it++) {
            int idx = tid + it * 128;
            int r   = idx >> 4;
            int d4  = (idx & 15) << 2;
            int jg  = kt0 + r;
            float4 kv = make_float4(0.f, 0.f, 0.f, 0.f);
            float4 vv = make_float4(0.f, 0.f, 0.f, 0.f);
            if (jg >= 0 && jg < S_) {
                kv = *(const float4*)(kb_ + (size_t)jg * D_ + d4);
                vv = *(const float4*)(vb_ + (size_t)jg * D_ + d4);
            }
            uint4 kt4, vt4;
            kt4.x = f2tf(kv.x); kt4.y = f2tf(kv.y); kt4.z = f2tf(kv.z); kt4.w = f2tf(kv.w);
            vt4.x = f2tf(vv.x); vt4.y = f2tf(vv.y); vt4.z = f2tf(vv.z); vt4.w = f2tf(vv.w);
            *(uint4*)&Ks[r][d4] = kt4;
            *(uint4*)&Vs[r][d4] = vt4;
        }
        if (tid < 64) {
            int jg = kt0 + tid;
            am_s[tid] = (jg >= 0 && jg < S_ && amask[b * S_ + jg] != 0) ? -10000.f : 0.f;
        }
        __syncthreads();

        float s[8][4];
        #pragma unroll
        for (int nt = 0; nt < 8; nt++)
            #pragma unroll
            for (int r = 0; r < 4; r++) s[nt][r] = 0.f;

        #pragma unroll
        for (int ks = 0; ks < 8; ks++) {
            const int k8 = ks * 8;
            #pragma unroll
            for (int nt = 0; nt < 8; nt++) {
                uint32_t b0 = Ks[nt * 8 + lg][k8 + lt];
                uint32_t b1 = Ks[nt * 8 + lg][k8 + lt + 4];
                mma8(s[nt], qf[ks][0], qf[ks][1], qf[ks][2], qf[ks][3], b0, b1);
            }
        }

        float tmax0 = -1e30f, tmax1 = -1e30f;
        #pragma unroll
        for (int nt = 0; nt < 8; nt++) {
            const int c0  = (nt << 3) + (lt << 1);
            const int jg0 = kt0 + c0, jg1 = jg0 + 1;
            const float am0 = am_s[c0], am1 = am_s[c0 + 1];
            s[nt][0] = (jg0 >= lo0 && jg0 <= hi0) ? s[nt][0] + am0 : -1e30f;
            s[nt][1] = (jg1 >= lo0 && jg1 <= hi0) ? s[nt][1] + am1 : -1e30f;
            s[nt][2] = (jg0 >= lo1 && jg0 <= hi1) ? s[nt][2] + am0 : -1e30f;
            s[nt][3] = (jg1 >= lo1 && jg1 <= hi1) ? s[nt][3] + am1 : -1e30f;
            tmax0 = fmaxf(tmax0, fmaxf(s[nt][0], s[nt][1]));
            tmax1 = fmaxf(tmax1, fmaxf(s[nt][2], s[nt][3]));
        }
        tmax0 = fmaxf(tmax0, __shfl_xor_sync(0xffffffffu, tmax0, 1, 32));
        tmax0 = fmaxf(tmax0, __shfl_xor_sync(0xffffffffu, tmax0, 2, 32));
        tmax1 = fmaxf(tmax1, __shfl_xor_sync(0xffffffffu, tmax1, 1, 32));
        tmax1 = fmaxf(tmax1, __shfl_xor_sync(0xffffffffu, tmax1, 2, 32));

        const float mn0 = fmaxf(m0r, tmax0), mn1 = fmaxf(m1r, tmax1);
        const float corr0 = __expf(m0r - mn0), corr1 = __expf(m1r - mn1);

        float rs0 = 0.f, rs1 = 0.f;
        #pragma unroll
        for (int nt = 0; nt < 8; nt++) {
            float e0 = (s[nt][0] > -1e29f) ? __expf(s[nt][0] - mn0) : 0.f;
            float e1 = (s[nt][1] > -1e29f) ? __expf(s[nt][1] - mn0) : 0.f;
            float e2 = (s[nt][2] > -1e29f) ? __expf(s[nt][2] - mn1) : 0.f;
            float e3 = (s[nt][3] > -1e29f) ? __expf(s[nt][3] - mn1) : 0.f;
            s[nt][0] = e0; s[nt][1] = e1; s[nt][2] = e2; s[nt][3] = e3;
            rs0 += e0 + e1; rs1 += e2 + e3;
        }
        rs0 += __shfl_xor_sync(0xffffffffu, rs0, 1, 32);
        rs0 += __shfl_xor_sync(0xffffffffu, rs0, 2, 32);
        rs1 += __shfl_xor_sync(0xffffffffu, rs1, 1, 32);
        rs1 += __shfl_xor_sync(0xffffffffu, rs1, 2, 32);

        l0 = l0 * corr0 + rs0; m0r = mn0;
        l1 = l1 * corr1 + rs1; m1r = mn1;
        #pragma unroll
        for (int vn = 0; vn < 8; vn++) {
            oacc[vn][0] *= corr0; oacc[vn][1] *= corr0;
            oacc[vn][2] *= corr1; oacc[vn][3] *= corr1;
        }

        const int s0l = (lg << 2) + (lt >> 1);
        const int s1l = s0l + 2;
        const bool odd = (lt & 1);
        #pragma unroll
        for (int kk = 0; kk < 8; kk++) {
            float t00 = __shfl_sync(0xffffffffu, s[kk][0], s0l, 32);
            float t01 = __shfl_sync(0xffffffffu, s[kk][1], s0l, 32);
            float t10 = __shfl_sync(0xffffffffu, s[kk][2], s0l, 32);
            float t11 = __shfl_sync(0xffffffffu, s[kk][3], s0l, 32);
            float t20 = __shfl_sync(0xffffffffu, s[kk][0], s1l, 32);
            float t21 = __shfl_sync(0xffffffffu, s[kk][1], s1l, 32);
            float t30 = __shfl_sync(0xffffffffu, s[kk][2], s1l, 32);
            float t31 = __shfl_sync(0xffffffffu, s[kk][3], s1l, 32);
            uint32_t a0 = f2tf(odd ? t01 : t00);
            uint32_t a1 = f2tf(odd ? t11 : t10);
            uint32_t a2 = f2tf(odd ? t21 : t20);
            uint32_t a3 = f2tf(odd ? t31 : t30);
            const int k8 = kk * 8;
            #pragma unroll
            for (int vn = 0; vn < 8; vn++) {
                uint32_t b0 = Vs[k8 + lt][vn * 8 + lg];
                uint32_t b1 = Vs[k8 + lt + 4][vn * 8 + lg];
                mma8(oacc[vn], a0, a1, a2, a3, b0, b1);
            }
        }
    }

    const float inv0 = 1.f / l0, inv1 = 1.f / l1;
    float* o0 = out + ((size_t)b * S_ + qi0) * E_ + h * D_;
    float* o1 = out + ((size_t)b * S_ + qi1) * E_ + h * D_;
    #pragma unroll
    for (int vn = 0; vn < 8; vn++) {
        const int col = vn * 8 + (lt << 1);
        float2 r0, r1;
        r0.x = oacc[vn][0] * inv0; r0.y = oacc[vn][1] * inv0;
        r1.x = oacc[vn][2] * inv1; r1.y = oacc[vn][3] * inv1;
        *(float2*)(o0 + col) = r0;
        *(float2*)(o1 + col) = r1;
    }
}

// ---------------------------------------------------------------------------
extern "C" void kernel_launch(void* const* d_in, const int* in_sizes, int n_in,
                              void* d_out, int out_size)
{
    const float* hs    = (const float*)d_in[0];   // [B,S,E]
    const int*   amask = (const int*)  d_in[1];   // [B,S]
    const float* qw    = (const float*)d_in[2];
    const float* qb    = (const float*)d_in[3];
    const float* kw    = (const float*)d_in[4];
    const float* kb    = (const float*)d_in[5];
    const float* vw    = (const float*)d_in[6];
    const float* vb    = (const float*)d_in[7];
    float* out = (float*)d_out;

    uint32_t *xh, *wqh, *wkh, *wvh;
    cudaGetSymbolAddress((void**)&xh,  g_xh);
    cudaGetSymbolAddress((void**)&wqh, g_wqh);
    cudaGetSymbolAddress((void**)&wkh, g_wkh);
    cudaGetSymbolAddress((void**)&wvh, g_wvh);

    const int nx4 = (B_ * S_ * E_) / 4;      // 2,097,152
    const int nw4 = (E_ * E_) / 4;           // 262,144
    conv_fp16<<<(nx4 + 255) / 256, 256>>>(hs, xh, nx4);
    conv_fp16<<<(nw4 + 255) / 256, 256>>>(qw, wqh, nw4);
    conv_fp16<<<(nw4 + 255) / 256, 256>>>(kw, wkh, nw4);
    conv_fp16<<<(nw4 + 255) / 256, 256>>>(vw, wvh, nw4);

    dim3 g1((B_ * S_) / 128, E_ / 128, 3);   // 64 x 8 x 3
    qkv_gemm_fp16<<<g1, 256>>>(qb, kb, vb);

    dim3 g2(S_ / 64, H_, B_);                // 64 x 16 x 2
    banded_attn_tc<<<g2, 128>>>(amask, out);
}